// round 10
// baseline (speedup 1.0000x reference)
#include <cuda_runtime.h>
#include <cuda_bf16.h>
#include <cstdint>

// ============================ problem constants =============================
static constexpr int V = 32000;
static constexpr int H = 4096;
static constexpr int NTOK = 4096;
static constexpr int IGNORE_INDEX = -100;

static constexpr int BM = 128;
static constexpr int BN = 256;
static constexpr int BK = 64;            // 64 bf16 = 128B rows (SW128 swizzle)
static constexpr int STAGES = 3;
static constexpr int CHUNKS = H / BK;    // 64
static constexpr int M_TILES = NTOK / BM;  // 32
static constexpr int V_TILES = V / BN;     // 125
static constexpr int THREADS = 256;        // 8 warps: 2 (m) x 4 (n), warp tile 64x64
static constexpr int A_STAGE_BYTES = BM * BK * 2;   // 16384
static constexpr int B_STAGE_BYTES = BN * BK * 2;   // 32768
static constexpr int STAGE_BYTES = A_STAGE_BYTES + B_STAGE_BYTES;  // 49152

// ============================ device scratch ================================
__device__ __align__(1024) __nv_bfloat16 g_Wb[(size_t)V * H];     // 262 MB
__device__ __align__(1024) __nv_bfloat16 g_Xb[(size_t)NTOK * H];  // 33 MB
__device__ float g_part_m[(size_t)V_TILES * NTOK];
__device__ float g_part_s[(size_t)V_TILES * NTOK];
__device__ float g_tgt_logit[NTOK];
__device__ float g_nll[NTOK];

// ============================ helpers =======================================
__device__ __forceinline__ uint32_t smem_u32(const void* p) {
    uint32_t a;
    asm("{ .reg .u64 t; cvta.to.shared.u64 t, %1; cvt.u32.u64 %0, t; }" : "=r"(a) : "l"(p));
    return a;
}
// Swizzle<3,4,3> for 128B rows: bits[6:4] ^= bits[9:7]
__device__ __forceinline__ uint32_t swz(uint32_t off) { return off ^ ((off >> 3) & 0x70); }

#define CP_ASYNC_16(dst, src) \
    asm volatile("cp.async.cg.shared.global [%0], [%1], 16;" :: "r"(dst), "l"(src) : "memory")
#define CP_COMMIT() asm volatile("cp.async.commit_group;" ::: "memory")
#define CP_WAIT(n)  asm volatile("cp.async.wait_group %0;" :: "n"(n) : "memory")

#define LDSM_X4(r0, r1, r2, r3, addr) \
    asm volatile("ldmatrix.sync.aligned.m8n8.x4.shared.b16 {%0,%1,%2,%3}, [%4];" \
        : "=r"(r0), "=r"(r1), "=r"(r2), "=r"(r3) : "r"(addr))

#define MMA_16816(c, a, b0, b1) \
    asm volatile("mma.sync.aligned.m16n8k16.row.col.f32.bf16.bf16.f32 " \
        "{%0,%1,%2,%3}, {%4,%5,%6,%7}, {%8,%9}, {%0,%1,%2,%3};" \
        : "+f"((c)[0]), "+f"((c)[1]), "+f"((c)[2]), "+f"((c)[3]) \
        : "r"((a)[0]), "r"((a)[1]), "r"((a)[2]), "r"((a)[3]), "r"(b0), "r"(b1))

// ============================ kernels =======================================

// fp32 -> bf16 conversion, 8 elems / thread / iter
__global__ void cvt_fp32_to_bf16_kernel(const float4* __restrict__ src,
                                        uint4* __restrict__ dst, int n8) {
    int i = blockIdx.x * blockDim.x + threadIdx.x;
    int stride = gridDim.x * blockDim.x;
    for (; i < n8; i += stride) {
        float4 a = src[2 * i];
        float4 b = src[2 * i + 1];
        __nv_bfloat162 p0 = __floats2bfloat162_rn(a.x, a.y);
        __nv_bfloat162 p1 = __floats2bfloat162_rn(a.z, a.w);
        __nv_bfloat162 p2 = __floats2bfloat162_rn(b.x, b.y);
        __nv_bfloat162 p3 = __floats2bfloat162_rn(b.z, b.w);
        uint4 u;
        u.x = *reinterpret_cast<unsigned int*>(&p0);
        u.y = *reinterpret_cast<unsigned int*>(&p1);
        u.z = *reinterpret_cast<unsigned int*>(&p2);
        u.w = *reinterpret_cast<unsigned int*>(&p3);
        dst[i] = u;
    }
}

// Exact fp32 target logit: one block per token, dot(x[tok], W[target]) + bias.
__global__ void __launch_bounds__(256)
tgt_logit_kernel(const float* __restrict__ X, const float* __restrict__ W,
                 const float* __restrict__ bias, const int* __restrict__ target) {
    __shared__ float sred[8];
    const int tok = blockIdx.x;
    const int t = target[tok];
    if (t < 0 || t >= V) {             // ignore_index or out of range
        if (threadIdx.x == 0) g_tgt_logit[tok] = 0.f;
        return;
    }
    const float4* xr = (const float4*)(X + (size_t)tok * H);
    const float4* wr = (const float4*)(W + (size_t)t * H);
    float s = 0.f;
    for (int i = threadIdx.x; i < H / 4; i += 256) {
        float4 a = xr[i], b = wr[i];
        s += a.x * b.x + a.y * b.y + a.z * b.z + a.w * b.w;
    }
#pragma unroll
    for (int o = 16; o; o >>= 1) s += __shfl_xor_sync(0xFFFFFFFFu, s, o);
    if ((threadIdx.x & 31) == 0) sred[threadIdx.x >> 5] = s;
    __syncthreads();
    if (threadIdx.x < 8) {
        s = sred[threadIdx.x];
#pragma unroll
        for (int o = 4; o; o >>= 1) s += __shfl_xor_sync(0xFFu, s, o);
        if (threadIdx.x == 0) g_tgt_logit[tok] = s + bias[t];
    }
}

// Fused GEMM + per-tile online softmax partials.
// 64x64 warp tiles (8 warps, BM=128 x BN=256): smem bytes per MMA drop from
// 192B to 128B, ldsm count per MMA drops 1.5x. 1 CTA/SM (144 KB smem).
__global__ void __launch_bounds__(THREADS, 1)
gemm_lse_kernel(const __nv_bfloat16* __restrict__ gX,
                const __nv_bfloat16* __restrict__ gW,
                const float* __restrict__ bias) {
    extern __shared__ __align__(128) char smem[];
    __shared__ float2 s_red[4][BM];

    const int tid = threadIdx.x;
    const int wid = tid >> 5, lane = tid & 31;
    const int wm = wid & 1, wn = wid >> 1;         // warp tile: rows wm*64, cols wn*64
    const int g = lane >> 2, tg = lane & 3;
    const int m_tile = blockIdx.x, v_tile = blockIdx.y;
    const int m0 = m_tile * BM, v0 = v_tile * BN;
    const uint32_t sbase = smem_u32(smem);

    // ---- ldmatrix addressing: (sS + row*128 + (hi16 ^ msk)) ^ (kk*32)
    const int lu = lane >> 3, lv = lane & 7;
    const uint32_t hi16 = (uint32_t)((lu >> 1) * 16);
    uint32_t foffA[4], foffB[4];
#pragma unroll
    for (int i = 0; i < 4; i++) {
        int row = wm * 64 + i * 16 + (lu & 1) * 8 + lv;
        foffA[i] = (uint32_t)(row * 128) + (hi16 ^ (uint32_t)((row & 7) * 16));
    }
#pragma unroll
    for (int bb = 0; bb < 4; bb++) {
        int row = wn * 64 + bb * 16 + (lu & 1) * 8 + lv;
        foffB[bb] = (uint32_t)(A_STAGE_BYTES + row * 128) + (hi16 ^ (uint32_t)((row & 7) * 16));
    }

    // ---- cp.async addressing (per thread, 2 running gmem ptrs)
    const int ld_row = tid >> 3, ld_kc = tid & 7;  // 32 rows per 'it' step
    const __nv_bfloat16* srcA = gX + (size_t)(m0 + ld_row) * H + ld_kc * 8;
    const __nv_bfloat16* srcW = gW + (size_t)(v0 + ld_row) * H + ld_kc * 8;
    const uint32_t dsw = swz((uint32_t)(ld_row * 128 + ld_kc * 16));  // +it*4096 swizzle-safe

    float acc[4][8][4];
#pragma unroll
    for (int i = 0; i < 4; i++)
#pragma unroll
        for (int j = 0; j < 8; j++)
#pragma unroll
            for (int q = 0; q < 4; q++) acc[i][j][q] = 0.f;

    // prologue: stages 0 and 1
#pragma unroll
    for (int s = 0; s < STAGES - 1; s++) {
        uint32_t dA = sbase + s * STAGE_BYTES + dsw;
#pragma unroll
        for (int it = 0; it < 4; it++)            // A: 128 rows
            CP_ASYNC_16(dA + it * 4096, srcA + it * 32 * H);
#pragma unroll
        for (int it = 0; it < 8; it++)            // B: 256 rows
            CP_ASYNC_16(dA + A_STAGE_BYTES + it * 4096, srcW + it * 32 * H);
        CP_COMMIT();
        srcA += BK; srcW += BK;
    }

    int s_cur = 0, s_ld = STAGES - 1;
    for (int c = 0; c < CHUNKS; c++) {
        CP_WAIT(STAGES - 2);
        __syncthreads();

        const bool doload = c + STAGES - 1 < CHUNKS;
        const uint32_t sS = sbase + s_cur * STAGE_BYTES;
        const uint32_t dL = sbase + s_ld * STAGE_BYTES + dsw;
        uint32_t baseA[4], baseB[4];
#pragma unroll
        for (int i = 0; i < 4; i++) baseA[i] = sS + foffA[i];
#pragma unroll
        for (int bb = 0; bb < 4; bb++) baseB[bb] = sS + foffB[bb];

#pragma unroll
        for (int kk = 0; kk < 4; kk++) {
            uint32_t Af[4][4];
#pragma unroll
            for (int i = 0; i < 4; i++)
                LDSM_X4(Af[i][0], Af[i][1], Af[i][2], Af[i][3], baseA[i] ^ (kk * 32));
            uint32_t Bf[4][4];
#pragma unroll
            for (int bb = 0; bb < 4; bb++)
                LDSM_X4(Bf[bb][0], Bf[bb][1], Bf[bb][2], Bf[bb][3], baseB[bb] ^ (kk * 32));

            if (kk == 0 && doload) {       // A rows of next stage
#pragma unroll
                for (int it = 0; it < 4; it++)
                    CP_ASYNC_16(dL + it * 4096, srcA + it * 32 * H);
            }
            if (kk == 1 && doload) {       // B rows 0..127
#pragma unroll
                for (int it = 0; it < 4; it++)
                    CP_ASYNC_16(dL + A_STAGE_BYTES + it * 4096, srcW + it * 32 * H);
            }
            if (kk == 2 && doload) {       // B rows 128..255
#pragma unroll
                for (int it = 4; it < 8; it++)
                    CP_ASYNC_16(dL + A_STAGE_BYTES + it * 4096, srcW + it * 32 * H);
            }

#pragma unroll
            for (int i = 0; i < 4; i++)
#pragma unroll
                for (int j = 0; j < 8; j++)
                    MMA_16816(acc[i][j], Af[i], Bf[j >> 1][j & 1], Bf[j >> 1][(j & 1) + 2]);
        }
        CP_COMMIT();
        srcA += BK; srcW += BK;
        s_cur = (s_cur == STAGES - 1) ? 0 : s_cur + 1;
        s_ld = (s_ld == STAGES - 1) ? 0 : s_ld + 1;
    }

    // ------------------------- epilogue: online softmax --------------------
    const float* bias_v = bias + v0 + wn * 64;
    float b2[8][2];
#pragma unroll
    for (int j = 0; j < 8; j++) {
        b2[j][0] = bias_v[j * 8 + 2 * tg];
        b2[j][1] = bias_v[j * 8 + 2 * tg + 1];
    }

#pragma unroll
    for (int i = 0; i < 4; i++) {
#pragma unroll
        for (int h = 0; h < 2; h++) {
            const int rl = wm * 64 + i * 16 + h * 8 + g;   // local row (0..127)
            float vals[16];
            float vmax = -1e30f;
#pragma unroll
            for (int j = 0; j < 8; j++)
#pragma unroll
                for (int q = 0; q < 2; q++) {
                    float vv = acc[i][j][h * 2 + q] + b2[j][q];
                    vals[j * 2 + q] = vv;
                    vmax = fmaxf(vmax, vv);
                }
            vmax = fmaxf(vmax, __shfl_xor_sync(0xFFFFFFFFu, vmax, 1));
            vmax = fmaxf(vmax, __shfl_xor_sync(0xFFFFFFFFu, vmax, 2));
            float s = 0.f;
#pragma unroll
            for (int x = 0; x < 16; x++) s += __expf(vals[x] - vmax);
            s += __shfl_xor_sync(0xFFFFFFFFu, s, 1);
            s += __shfl_xor_sync(0xFFFFFFFFu, s, 2);

            if (tg == 0) s_red[wn][rl] = make_float2(vmax, s);
        }
    }
    __syncthreads();
    if (tid < BM) {
        float m = -1e30f, s = 0.f;
#pragma unroll
        for (int p = 0; p < 4; p++) {
            float2 pr = s_red[p][tid];
            float nm = fmaxf(m, pr.x);
            s = s * __expf(m - nm) + pr.y * __expf(pr.x - nm);
            m = nm;
        }
        g_part_m[(size_t)v_tile * NTOK + m0 + tid] = m;
        g_part_s[(size_t)v_tile * NTOK + m0 + tid] = s;
    }
}

// one warp per token: merge V_TILES partial (m, s) pairs -> nll
__global__ void lse_merge_kernel(const int* __restrict__ target) {
    int tok = blockIdx.x * 8 + (threadIdx.x >> 5);
    int lane = threadIdx.x & 31;
    float m = -1e30f, s = 0.f;
    for (int p = lane; p < V_TILES; p += 32) {
        float pm = g_part_m[(size_t)p * NTOK + tok];
        float ps = g_part_s[(size_t)p * NTOK + tok];
        float nm = fmaxf(m, pm);
        s = s * expf(m - nm) + ps * expf(pm - nm);
        m = nm;
    }
#pragma unroll
    for (int o = 16; o; o >>= 1) {
        float mo = __shfl_xor_sync(0xFFFFFFFFu, m, o);
        float so = __shfl_xor_sync(0xFFFFFFFFu, s, o);
        float nm = fmaxf(m, mo);
        s = s * expf(m - nm) + so * expf(mo - nm);
        m = nm;
    }
    if (lane == 0) {
        float lse = m + logf(s);
        int t = target[tok];
        g_nll[tok] = (t == IGNORE_INDEX) ? 0.f : (lse - g_tgt_logit[tok]);
    }
}

__global__ void finalize_kernel(const int* __restrict__ target, float* __restrict__ out) {
    __shared__ float ssum[1024];
    __shared__ int scnt[1024];
    int tid = threadIdx.x;
    float s = 0.f;
    int c = 0;
    for (int i = tid; i < NTOK; i += 1024) {
        s += g_nll[i];
        c += (target[i] != IGNORE_INDEX);
    }
    ssum[tid] = s;
    scnt[tid] = c;
    __syncthreads();
    for (int o = 512; o; o >>= 1) {
        if (tid < o) { ssum[tid] += ssum[tid + o]; scnt[tid] += scnt[tid + o]; }
        __syncthreads();
    }
    if (tid == 0) out[0] = ssum[0] / (float)scnt[0];
}

// ============================ host launch ===================================
extern "C" void kernel_launch(void* const* d_in, const int* in_sizes, int n_in,
                              void* d_out, int out_size) {
    const float* W = (const float*)d_in[0];
    const float* X = (const float*)d_in[1];
    const int* target = (const int*)d_in[2];     // int32 (jax demotes int64)
    const float* bias = (const float*)d_in[3];
    float* out = (float*)d_out;

    void* wb = nullptr; cudaGetSymbolAddress(&wb, g_Wb);
    void* xb = nullptr; cudaGetSymbolAddress(&xb, g_Xb);

    const int SMEM_SZ = STAGES * STAGE_BYTES;   // 144 KB
    cudaFuncSetAttribute(gemm_lse_kernel,
                         cudaFuncAttributeMaxDynamicSharedMemorySize, SMEM_SZ);

    // 1. convert W and X to bf16
    cvt_fp32_to_bf16_kernel<<<2048, 256>>>((const float4*)W, (uint4*)wb, (V * H) / 8);
    cvt_fp32_to_bf16_kernel<<<512, 256>>>((const float4*)X, (uint4*)xb, (NTOK * H) / 8);

    // 1b. exact fp32 target logits from the original inputs
    tgt_logit_kernel<<<NTOK, 256>>>(X, W, bias, target);

    // 2. fused GEMM + partial LSE. x = m_tile (fast) so CTAs sharing a W slab
    //    run concurrently and X stays L2-resident.
    gemm_lse_kernel<<<dim3(M_TILES, V_TILES), THREADS, SMEM_SZ>>>(
        (const __nv_bfloat16*)xb, (const __nv_bfloat16*)wb, bias);

    // 3. merge partials (one warp per token), then deterministic mean
    lse_merge_kernel<<<NTOK / 8, 256>>>(target);
    finalize_kernel<<<1, 1024>>>(target, out);
}

// round 11
// speedup vs baseline: 1.0772x; 1.0772x over previous
#include <cuda_runtime.h>
#include <cuda_bf16.h>
#include <cstdint>

// ============================ problem constants =============================
static constexpr int V = 32000;
static constexpr int H = 4096;
static constexpr int NTOK = 4096;
static constexpr int IGNORE_INDEX = -100;

static constexpr int BM = 128;
static constexpr int BN = 128;
static constexpr int BK = 64;            // 64 bf16 = 128B rows (SW128 swizzle)
static constexpr int STAGES = 3;
static constexpr int CHUNKS = H / BK;    // 64
static constexpr int M_TILES = NTOK / BM;  // 32
static constexpr int V_TILES = V / BN;     // 250
static constexpr int THREADS = 256;        // 8 warps: 4 (m) x 2 (n)
static constexpr int A_STAGE_BYTES = BM * BK * 2;   // 16384
static constexpr int B_STAGE_BYTES = BN * BK * 2;   // 16384
static constexpr int STAGE_BYTES = A_STAGE_BYTES + B_STAGE_BYTES;  // 32768

// ============================ device scratch ================================
__device__ __align__(1024) __nv_bfloat16 g_Wb[(size_t)V * H];     // 262 MB
__device__ __align__(1024) __nv_bfloat16 g_Xb[(size_t)NTOK * H];  // 33 MB
__device__ float g_part_m[(size_t)V_TILES * NTOK];
__device__ float g_part_s[(size_t)V_TILES * NTOK];
__device__ float g_tgt_logit[NTOK];
__device__ float g_nll[NTOK];

// ============================ helpers =======================================
__device__ __forceinline__ uint32_t smem_u32(const void* p) {
    uint32_t a;
    asm("{ .reg .u64 t; cvta.to.shared.u64 t, %1; cvt.u32.u64 %0, t; }" : "=r"(a) : "l"(p));
    return a;
}
// Swizzle<3,4,3> for 128B rows: bits[6:4] ^= bits[9:7]
__device__ __forceinline__ uint32_t swz(uint32_t off) { return off ^ ((off >> 3) & 0x70); }

#define CP_ASYNC_16(dst, src) \
    asm volatile("cp.async.cg.shared.global [%0], [%1], 16;" :: "r"(dst), "l"(src) : "memory")
#define CP_COMMIT() asm volatile("cp.async.commit_group;" ::: "memory")
#define CP_WAIT(n)  asm volatile("cp.async.wait_group %0;" :: "n"(n) : "memory")

#define LDSM_X4(r0, r1, r2, r3, addr) \
    asm volatile("ldmatrix.sync.aligned.m8n8.x4.shared.b16 {%0,%1,%2,%3}, [%4];" \
        : "=r"(r0), "=r"(r1), "=r"(r2), "=r"(r3) : "r"(addr))

#define MMA_16816(c, a, b0, b1) \
    asm volatile("mma.sync.aligned.m16n8k16.row.col.f32.bf16.bf16.f32 " \
        "{%0,%1,%2,%3}, {%4,%5,%6,%7}, {%8,%9}, {%0,%1,%2,%3};" \
        : "+f"((c)[0]), "+f"((c)[1]), "+f"((c)[2]), "+f"((c)[3]) \
        : "r"((a)[0]), "r"((a)[1]), "r"((a)[2]), "r"((a)[3]), "r"(b0), "r"(b1))

// ldmatrix.x4 lane address: 4 8x8 tiles covering (row0..row0+15) x (k16 chunk kk)
__device__ __forceinline__ uint32_t ldsm_addr(uint32_t base, int row0, int lane, int kk) {
    int u = lane >> 3, v = lane & 7;
    int row = row0 + (u & 1) * 8 + v;
    int kb = kk * 32 + (u >> 1) * 16;
    return base + swz((uint32_t)(row * 128 + kb));
}

// ============================ kernels =======================================

// fp32 -> bf16 conversion, 8 elems / thread / iter
__global__ void cvt_fp32_to_bf16_kernel(const float4* __restrict__ src,
                                        uint4* __restrict__ dst, int n8) {
    int i = blockIdx.x * blockDim.x + threadIdx.x;
    int stride = gridDim.x * blockDim.x;
    for (; i < n8; i += stride) {
        float4 a = src[2 * i];
        float4 b = src[2 * i + 1];
        __nv_bfloat162 p0 = __floats2bfloat162_rn(a.x, a.y);
        __nv_bfloat162 p1 = __floats2bfloat162_rn(a.z, a.w);
        __nv_bfloat162 p2 = __floats2bfloat162_rn(b.x, b.y);
        __nv_bfloat162 p3 = __floats2bfloat162_rn(b.z, b.w);
        uint4 u;
        u.x = *reinterpret_cast<unsigned int*>(&p0);
        u.y = *reinterpret_cast<unsigned int*>(&p1);
        u.z = *reinterpret_cast<unsigned int*>(&p2);
        u.w = *reinterpret_cast<unsigned int*>(&p3);
        dst[i] = u;
    }
}

// Fused GEMM + per-tile online softmax partials + in-tile target-logit capture.
// GEMM mainloop is byte-identical to the 2480us champion; only the epilogue
// gains the (rare) target capture, replacing the separate fp32 tgt kernel.
__global__ void __launch_bounds__(THREADS, 2)
gemm_lse_kernel(const __nv_bfloat16* __restrict__ gX,
                const __nv_bfloat16* __restrict__ gW,
                const float* __restrict__ bias,
                const int* __restrict__ target) {
    extern __shared__ __align__(128) char smem[];
    __shared__ float2 s_red[2][BM];

    const int tid = threadIdx.x;
    const int wid = tid >> 5, lane = tid & 31;
    const int wm = wid & 3, wn = wid >> 2;         // warp tile: rows wm*32, cols wn*64
    const int g = lane >> 2, tg = lane & 3;
    const int m_tile = blockIdx.x, v_tile = blockIdx.y;
    const int m0 = m_tile * BM, v0 = v_tile * BN;
    const uint32_t sbase = smem_u32(smem);

    float acc[2][8][4];
#pragma unroll
    for (int i = 0; i < 2; i++)
#pragma unroll
        for (int j = 0; j < 8; j++)
#pragma unroll
            for (int q = 0; q < 4; q++) acc[i][j][q] = 0.f;

    // ---- precomputed cp.async addressing (per thread, 2 running gmem ptrs)
    const int ld_row = tid >> 3, ld_kc = tid & 7;  // 32 rows per 'it' step
    const __nv_bfloat16* srcA = gX + (size_t)(m0 + ld_row) * H + ld_kc * 8;
    const __nv_bfloat16* srcW = gW + (size_t)(v0 + ld_row) * H + ld_kc * 8;
    const uint32_t dsw = swz((uint32_t)(ld_row * 128 + ld_kc * 16));  // +it*4096 swizzle-safe

    // prologue: stages 0 and 1
#pragma unroll
    for (int s = 0; s < STAGES - 1; s++) {
        uint32_t dA = sbase + s * STAGE_BYTES + dsw;
#pragma unroll
        for (int it = 0; it < 4; it++)
            CP_ASYNC_16(dA + it * 4096, srcA + it * 32 * H);
#pragma unroll
        for (int it = 0; it < 4; it++)
            CP_ASYNC_16(dA + A_STAGE_BYTES + it * 4096, srcW + it * 32 * H);
        CP_COMMIT();
        srcA += BK; srcW += BK;
    }

    int s_cur = 0, s_ld = STAGES - 1;
    for (int c = 0; c < CHUNKS; c++) {
        CP_WAIT(STAGES - 2);
        __syncthreads();

        int cn = c + STAGES - 1;
        const bool doload = cn < CHUNKS;
        const uint32_t sA = sbase + s_cur * STAGE_BYTES;
        const uint32_t sB = sA + A_STAGE_BYTES;
        const uint32_t dL = sbase + s_ld * STAGE_BYTES + dsw;

#pragma unroll
        for (int kk = 0; kk < 4; kk++) {
            uint32_t Af[2][4];
#pragma unroll
            for (int i = 0; i < 2; i++)
                LDSM_X4(Af[i][0], Af[i][1], Af[i][2], Af[i][3],
                        ldsm_addr(sA, wm * 32 + i * 16, lane, kk));
            uint32_t Bf[4][4];
#pragma unroll
            for (int bb = 0; bb < 4; bb++)
                LDSM_X4(Bf[bb][0], Bf[bb][1], Bf[bb][2], Bf[bb][3],
                        ldsm_addr(sB, wn * 64 + bb * 16, lane, kk));

            if (kk == 0 && doload) {       // A-half of next-stage load
#pragma unroll
                for (int it = 0; it < 4; it++)
                    CP_ASYNC_16(dL + it * 4096, srcA + it * 32 * H);
            }
            if (kk == 1 && doload) {       // B-half of next-stage load
#pragma unroll
                for (int it = 0; it < 4; it++)
                    CP_ASYNC_16(dL + A_STAGE_BYTES + it * 4096, srcW + it * 32 * H);
            }

#pragma unroll
            for (int i = 0; i < 2; i++)
#pragma unroll
                for (int j = 0; j < 8; j++)
                    MMA_16816(acc[i][j], Af[i], Bf[j >> 1][j & 1], Bf[j >> 1][(j & 1) + 2]);
        }
        CP_COMMIT();
        srcA += BK; srcW += BK;
        s_cur = (s_cur == STAGES - 1) ? 0 : s_cur + 1;
        s_ld = (s_ld == STAGES - 1) ? 0 : s_ld + 1;
    }

    // ------------------------- epilogue: online softmax --------------------
    const float* bias_v = bias + v0 + wn * 64;
    float b2[8][2];
#pragma unroll
    for (int j = 0; j < 8; j++) {
        b2[j][0] = bias_v[j * 8 + 2 * tg];
        b2[j][1] = bias_v[j * 8 + 2 * tg + 1];
    }

#pragma unroll
    for (int i = 0; i < 2; i++) {
#pragma unroll
        for (int h = 0; h < 2; h++) {
            const int rl = wm * 32 + i * 16 + h * 8 + g;   // local row
            float vals[16];
            float vmax = -1e30f;
#pragma unroll
            for (int j = 0; j < 8; j++)
#pragma unroll
                for (int q = 0; q < 2; q++) {
                    float vv = acc[i][j][h * 2 + q] + b2[j][q];
                    vals[j * 2 + q] = vv;
                    vmax = fmaxf(vmax, vv);
                }
            vmax = fmaxf(vmax, __shfl_xor_sync(0xFFFFFFFFu, vmax, 1));
            vmax = fmaxf(vmax, __shfl_xor_sync(0xFFFFFFFFu, vmax, 2));
            float s = 0.f;
#pragma unroll
            for (int x = 0; x < 16; x++) s += __expf(vals[x] - vmax);
            s += __shfl_xor_sync(0xFFFFFFFFu, s, 1);
            s += __shfl_xor_sync(0xFFFFFFFFu, s, 2);

            // in-tile target-logit capture (int32 targets; unique writer)
            const int t = target[m0 + rl];
            const int tloc = t - v0 - wn * 64;     // col within this warp's slice
            if (tloc >= 0 && tloc < 64) {
#pragma unroll
                for (int j = 0; j < 8; j++)
#pragma unroll
                    for (int q = 0; q < 2; q++)
                        if (j * 8 + 2 * tg + q == tloc)
                            g_tgt_logit[m0 + rl] = vals[j * 2 + q];
            }

            if (tg == 0) s_red[wn][rl] = make_float2(vmax, s);
        }
    }
    __syncthreads();
    if (tid < BM) {
        float2 p0 = s_red[0][tid], p1 = s_red[1][tid];
        float m = fmaxf(p0.x, p1.x);
        float s = p0.y * __expf(p0.x - m) + p1.y * __expf(p1.x - m);
        g_part_m[(size_t)v_tile * NTOK + m0 + tid] = m;
        g_part_s[(size_t)v_tile * NTOK + m0 + tid] = s;
    }
}

// one warp per token: merge V_TILES partial (m, s) pairs -> nll
__global__ void lse_merge_kernel(const int* __restrict__ target) {
    int tok = blockIdx.x * 8 + (threadIdx.x >> 5);
    int lane = threadIdx.x & 31;
    float m = -1e30f, s = 0.f;
    for (int p = lane; p < V_TILES; p += 32) {
        float pm = g_part_m[(size_t)p * NTOK + tok];
        float ps = g_part_s[(size_t)p * NTOK + tok];
        float nm = fmaxf(m, pm);
        s = s * expf(m - nm) + ps * expf(pm - nm);
        m = nm;
    }
#pragma unroll
    for (int o = 16; o; o >>= 1) {
        float mo = __shfl_xor_sync(0xFFFFFFFFu, m, o);
        float so = __shfl_xor_sync(0xFFFFFFFFu, s, o);
        float nm = fmaxf(m, mo);
        s = s * expf(m - nm) + so * expf(mo - nm);
        m = nm;
    }
    if (lane == 0) {
        float lse = m + logf(s);
        int t = target[tok];
        g_nll[tok] = (t == IGNORE_INDEX) ? 0.f : (lse - g_tgt_logit[tok]);
    }
}

__global__ void finalize_kernel(const int* __restrict__ target, float* __restrict__ out) {
    __shared__ float ssum[1024];
    __shared__ int scnt[1024];
    int tid = threadIdx.x;
    float s = 0.f;
    int c = 0;
    for (int i = tid; i < NTOK; i += 1024) {
        s += g_nll[i];
        c += (target[i] != IGNORE_INDEX);
    }
    ssum[tid] = s;
    scnt[tid] = c;
    __syncthreads();
    for (int o = 512; o; o >>= 1) {
        if (tid < o) { ssum[tid] += ssum[tid + o]; scnt[tid] += scnt[tid + o]; }
        __syncthreads();
    }
    if (tid == 0) out[0] = ssum[0] / (float)scnt[0];
}

// ============================ host launch ===================================
extern "C" void kernel_launch(void* const* d_in, const int* in_sizes, int n_in,
                              void* d_out, int out_size) {
    const float* W = (const float*)d_in[0];
    const float* X = (const float*)d_in[1];
    const int* target = (const int*)d_in[2];     // int32 (jax demotes int64)
    const float* bias = (const float*)d_in[3];
    float* out = (float*)d_out;

    void* wb = nullptr; cudaGetSymbolAddress(&wb, g_Wb);
    void* xb = nullptr; cudaGetSymbolAddress(&xb, g_Xb);

    const int SMEM_SZ = STAGES * STAGE_BYTES;   // 96 KB
    cudaFuncSetAttribute(gemm_lse_kernel,
                         cudaFuncAttributeMaxDynamicSharedMemorySize, SMEM_SZ);

    // 1. convert W and X to bf16
    cvt_fp32_to_bf16_kernel<<<2048, 256>>>((const float4*)W, (uint4*)wb, (V * H) / 8);
    cvt_fp32_to_bf16_kernel<<<512, 256>>>((const float4*)X, (uint4*)xb, (NTOK * H) / 8);

    // 2. fused GEMM + partial LSE + target-logit capture. x = m_tile (fast) so
    //    CTAs sharing a W slab run concurrently and X stays L2-resident.
    gemm_lse_kernel<<<dim3(M_TILES, V_TILES), THREADS, SMEM_SZ>>>(
        (const __nv_bfloat16*)xb, (const __nv_bfloat16*)wb, bias, target);

    // 3. merge partials (one warp per token), then deterministic mean
    lse_merge_kernel<<<NTOK / 8, 256>>>(target);
    finalize_kernel<<<1, 1024>>>(target, out);
}

// round 12
// speedup vs baseline: 1.1303x; 1.0493x over previous
#include <cuda_runtime.h>
#include <cuda_bf16.h>
#include <cstdint>

// ============================ problem constants =============================
static constexpr int V = 32000;
static constexpr int H = 4096;
static constexpr int NTOK = 4096;
static constexpr int IGNORE_INDEX = -100;

static constexpr int BM = 128;
static constexpr int BN = 128;
static constexpr int BK = 64;            // 64 bf16 = 128B rows (SW128 swizzle)
static constexpr int STAGES = 3;
static constexpr int CHUNKS = H / BK;    // 64
static constexpr int M_TILES = NTOK / BM;  // 32
static constexpr int V_TILES = V / BN;     // 250
static constexpr int THREADS = 256;        // 8 warps: 4 (m) x 2 (n)
static constexpr int A_STAGE_BYTES = BM * BK * 2;   // 16384
static constexpr int B_STAGE_BYTES = BN * BK * 2;   // 16384
static constexpr int STAGE_BYTES = A_STAGE_BYTES + B_STAGE_BYTES;  // 32768

// ============================ device scratch ================================
__device__ __align__(1024) __nv_bfloat16 g_Wb[(size_t)V * H];     // 262 MB
__device__ __align__(1024) __nv_bfloat16 g_Xb[(size_t)NTOK * H];  // 33 MB
// Transposed partials: [tok][v_tile] so lse_merge lanes read consecutive floats
__device__ float g_part_m[(size_t)NTOK * V_TILES];
__device__ float g_part_s[(size_t)NTOK * V_TILES];
__device__ float g_tgt_logit[NTOK];
__device__ float g_nll[NTOK];

// ============================ helpers =======================================
__device__ __forceinline__ uint32_t smem_u32(const void* p) {
    uint32_t a;
    asm("{ .reg .u64 t; cvta.to.shared.u64 t, %1; cvt.u32.u64 %0, t; }" : "=r"(a) : "l"(p));
    return a;
}
// Swizzle<3,4,3> for 128B rows: bits[6:4] ^= bits[9:7]
__device__ __forceinline__ uint32_t swz(uint32_t off) { return off ^ ((off >> 3) & 0x70); }

#define CP_ASYNC_16(dst, src) \
    asm volatile("cp.async.cg.shared.global [%0], [%1], 16;" :: "r"(dst), "l"(src) : "memory")
#define CP_COMMIT() asm volatile("cp.async.commit_group;" ::: "memory")
#define CP_WAIT(n)  asm volatile("cp.async.wait_group %0;" :: "n"(n) : "memory")

#define LDSM_X4(r0, r1, r2, r3, addr) \
    asm volatile("ldmatrix.sync.aligned.m8n8.x4.shared.b16 {%0,%1,%2,%3}, [%4];" \
        : "=r"(r0), "=r"(r1), "=r"(r2), "=r"(r3) : "r"(addr))

#define MMA_16816(c, a, b0, b1) \
    asm volatile("mma.sync.aligned.m16n8k16.row.col.f32.bf16.bf16.f32 " \
        "{%0,%1,%2,%3}, {%4,%5,%6,%7}, {%8,%9}, {%0,%1,%2,%3};" \
        : "+f"((c)[0]), "+f"((c)[1]), "+f"((c)[2]), "+f"((c)[3]) \
        : "r"((a)[0]), "r"((a)[1]), "r"((a)[2]), "r"((a)[3]), "r"(b0), "r"(b1))

// ldmatrix.x4 lane address: 4 8x8 tiles covering (row0..row0+15) x (k16 chunk kk)
__device__ __forceinline__ uint32_t ldsm_addr(uint32_t base, int row0, int lane, int kk) {
    int u = lane >> 3, v = lane & 7;
    int row = row0 + (u & 1) * 8 + v;
    int kb = kk * 32 + (u >> 1) * 16;
    return base + swz((uint32_t)(row * 128 + kb));
}

// ============================ kernels =======================================

// fp32 -> bf16 conversion, 8 elems / thread / iter
__global__ void cvt_fp32_to_bf16_kernel(const float4* __restrict__ src,
                                        uint4* __restrict__ dst, int n8) {
    int i = blockIdx.x * blockDim.x + threadIdx.x;
    int stride = gridDim.x * blockDim.x;
    for (; i < n8; i += stride) {
        float4 a = src[2 * i];
        float4 b = src[2 * i + 1];
        __nv_bfloat162 p0 = __floats2bfloat162_rn(a.x, a.y);
        __nv_bfloat162 p1 = __floats2bfloat162_rn(a.z, a.w);
        __nv_bfloat162 p2 = __floats2bfloat162_rn(b.x, b.y);
        __nv_bfloat162 p3 = __floats2bfloat162_rn(b.z, b.w);
        uint4 u;
        u.x = *reinterpret_cast<unsigned int*>(&p0);
        u.y = *reinterpret_cast<unsigned int*>(&p1);
        u.z = *reinterpret_cast<unsigned int*>(&p2);
        u.w = *reinterpret_cast<unsigned int*>(&p3);
        dst[i] = u;
    }
}

// Fused GEMM + per-tile online softmax partials + in-tile target-logit capture.
__global__ void __launch_bounds__(THREADS, 2)
gemm_lse_kernel(const __nv_bfloat16* __restrict__ gX,
                const __nv_bfloat16* __restrict__ gW,
                const float* __restrict__ bias,
                const int* __restrict__ target) {
    extern __shared__ __align__(128) char smem[];
    __shared__ float2 s_red[2][BM];

    const int tid = threadIdx.x;
    const int wid = tid >> 5, lane = tid & 31;
    const int wm = wid & 3, wn = wid >> 2;         // warp tile: rows wm*32, cols wn*64
    const int g = lane >> 2, tg = lane & 3;
    const int m_tile = blockIdx.x, v_tile = blockIdx.y;
    const int m0 = m_tile * BM, v0 = v_tile * BN;
    const uint32_t sbase = smem_u32(smem);

    float acc[2][8][4];
#pragma unroll
    for (int i = 0; i < 2; i++)
#pragma unroll
        for (int j = 0; j < 8; j++)
#pragma unroll
            for (int q = 0; q < 4; q++) acc[i][j][q] = 0.f;

    // ---- precomputed cp.async addressing (per thread, 2 running gmem ptrs)
    const int ld_row = tid >> 3, ld_kc = tid & 7;  // 32 rows per 'it' step
    const __nv_bfloat16* srcA = gX + (size_t)(m0 + ld_row) * H + ld_kc * 8;
    const __nv_bfloat16* srcW = gW + (size_t)(v0 + ld_row) * H + ld_kc * 8;
    const uint32_t dsw = swz((uint32_t)(ld_row * 128 + ld_kc * 16));  // +it*4096 swizzle-safe

    // prologue: stages 0 and 1
#pragma unroll
    for (int s = 0; s < STAGES - 1; s++) {
        uint32_t dA = sbase + s * STAGE_BYTES + dsw;
#pragma unroll
        for (int it = 0; it < 4; it++)
            CP_ASYNC_16(dA + it * 4096, srcA + it * 32 * H);
#pragma unroll
        for (int it = 0; it < 4; it++)
            CP_ASYNC_16(dA + A_STAGE_BYTES + it * 4096, srcW + it * 32 * H);
        CP_COMMIT();
        srcA += BK; srcW += BK;
    }

    int s_cur = 0, s_ld = STAGES - 1;
    for (int c = 0; c < CHUNKS; c++) {
        CP_WAIT(STAGES - 2);
        __syncthreads();

        int cn = c + STAGES - 1;
        const bool doload = cn < CHUNKS;
        const uint32_t sA = sbase + s_cur * STAGE_BYTES;
        const uint32_t sB = sA + A_STAGE_BYTES;
        const uint32_t dL = sbase + s_ld * STAGE_BYTES + dsw;

#pragma unroll
        for (int kk = 0; kk < 4; kk++) {
            uint32_t Af[2][4];
#pragma unroll
            for (int i = 0; i < 2; i++)
                LDSM_X4(Af[i][0], Af[i][1], Af[i][2], Af[i][3],
                        ldsm_addr(sA, wm * 32 + i * 16, lane, kk));
            uint32_t Bf[4][4];
#pragma unroll
            for (int bb = 0; bb < 4; bb++)
                LDSM_X4(Bf[bb][0], Bf[bb][1], Bf[bb][2], Bf[bb][3],
                        ldsm_addr(sB, wn * 64 + bb * 16, lane, kk));

            if (kk == 0 && doload) {       // A-half of next-stage load
#pragma unroll
                for (int it = 0; it < 4; it++)
                    CP_ASYNC_16(dL + it * 4096, srcA + it * 32 * H);
            }
            if (kk == 1 && doload) {       // B-half of next-stage load
#pragma unroll
                for (int it = 0; it < 4; it++)
                    CP_ASYNC_16(dL + A_STAGE_BYTES + it * 4096, srcW + it * 32 * H);
            }

#pragma unroll
            for (int i = 0; i < 2; i++)
#pragma unroll
                for (int j = 0; j < 8; j++)
                    MMA_16816(acc[i][j], Af[i], Bf[j >> 1][j & 1], Bf[j >> 1][(j & 1) + 2]);
        }
        CP_COMMIT();
        srcA += BK; srcW += BK;
        s_cur = (s_cur == STAGES - 1) ? 0 : s_cur + 1;
        s_ld = (s_ld == STAGES - 1) ? 0 : s_ld + 1;
    }

    // ------------------------- epilogue: online softmax --------------------
    const float* bias_v = bias + v0 + wn * 64;
    float b2[8][2];
#pragma unroll
    for (int j = 0; j < 8; j++) {
        b2[j][0] = bias_v[j * 8 + 2 * tg];
        b2[j][1] = bias_v[j * 8 + 2 * tg + 1];
    }

#pragma unroll
    for (int i = 0; i < 2; i++) {
#pragma unroll
        for (int h = 0; h < 2; h++) {
            const int rl = wm * 32 + i * 16 + h * 8 + g;   // local row
            float vals[16];
            float vmax = -1e30f;
#pragma unroll
            for (int j = 0; j < 8; j++)
#pragma unroll
                for (int q = 0; q < 2; q++) {
                    float vv = acc[i][j][h * 2 + q] + b2[j][q];
                    vals[j * 2 + q] = vv;
                    vmax = fmaxf(vmax, vv);
                }
            vmax = fmaxf(vmax, __shfl_xor_sync(0xFFFFFFFFu, vmax, 1));
            vmax = fmaxf(vmax, __shfl_xor_sync(0xFFFFFFFFu, vmax, 2));
            float s = 0.f;
#pragma unroll
            for (int x = 0; x < 16; x++) s += __expf(vals[x] - vmax);
            s += __shfl_xor_sync(0xFFFFFFFFu, s, 1);
            s += __shfl_xor_sync(0xFFFFFFFFu, s, 2);

            // in-tile target-logit capture via direct index arithmetic:
            // col = j*8 + 2*tg + q  ->  owner tg = (tloc>>1)&3, j = tloc>>3, q = tloc&1
            const int t = target[m0 + rl];
            const int tloc = t - v0 - wn * 64;     // col within this warp's 64-col slice
            if (tloc >= 0 && tloc < 64 && ((tloc >> 1) & 3) == tg) {
                const int jj = tloc >> 3, qq = tloc & 1;
                g_tgt_logit[m0 + rl] = vals[jj * 2 + qq];
            }

            if (tg == 0) s_red[wn][rl] = make_float2(vmax, s);
        }
    }
    __syncthreads();
    if (tid < BM) {
        float2 p0 = s_red[0][tid], p1 = s_red[1][tid];
        float m = fmaxf(p0.x, p1.x);
        float s = p0.y * __expf(p0.x - m) + p1.y * __expf(p1.x - m);
        // transposed layout: [tok][v_tile]
        g_part_m[(size_t)(m0 + tid) * V_TILES + v_tile] = m;
        g_part_s[(size_t)(m0 + tid) * V_TILES + v_tile] = s;
    }
}

// one warp per token: merge V_TILES partial (m, s) pairs -> nll (coalesced reads)
__global__ void lse_merge_kernel(const int* __restrict__ target) {
    int tok = blockIdx.x * 8 + (threadIdx.x >> 5);
    int lane = threadIdx.x & 31;
    const float* pm_row = g_part_m + (size_t)tok * V_TILES;
    const float* ps_row = g_part_s + (size_t)tok * V_TILES;
    float m = -1e30f, s = 0.f;
    for (int p = lane; p < V_TILES; p += 32) {
        float pm = pm_row[p];
        float ps = ps_row[p];
        float nm = fmaxf(m, pm);
        s = s * expf(m - nm) + ps * expf(pm - nm);
        m = nm;
    }
#pragma unroll
    for (int o = 16; o; o >>= 1) {
        float mo = __shfl_xor_sync(0xFFFFFFFFu, m, o);
        float so = __shfl_xor_sync(0xFFFFFFFFu, s, o);
        float nm = fmaxf(m, mo);
        s = s * expf(m - nm) + so * expf(mo - nm);
        m = nm;
    }
    if (lane == 0) {
        float lse = m + logf(s);
        int t = target[tok];
        g_nll[tok] = (t == IGNORE_INDEX) ? 0.f : (lse - g_tgt_logit[tok]);
    }
}

__global__ void finalize_kernel(const int* __restrict__ target, float* __restrict__ out) {
    __shared__ float ssum[1024];
    __shared__ int scnt[1024];
    int tid = threadIdx.x;
    float s = 0.f;
    int c = 0;
    for (int i = tid; i < NTOK; i += 1024) {
        s += g_nll[i];
        c += (target[i] != IGNORE_INDEX);
    }
    ssum[tid] = s;
    scnt[tid] = c;
    __syncthreads();
    for (int o = 512; o; o >>= 1) {
        if (tid < o) { ssum[tid] += ssum[tid + o]; scnt[tid] += scnt[tid + o]; }
        __syncthreads();
    }
    if (tid == 0) out[0] = ssum[0] / (float)scnt[0];
}

// ============================ host launch ===================================
extern "C" void kernel_launch(void* const* d_in, const int* in_sizes, int n_in,
                              void* d_out, int out_size) {
    const float* W = (const float*)d_in[0];
    const float* X = (const float*)d_in[1];
    const int* target = (const int*)d_in[2];     // int32 (jax demotes int64)
    const float* bias = (const float*)d_in[3];
    float* out = (float*)d_out;

    void* wb = nullptr; cudaGetSymbolAddress(&wb, g_Wb);
    void* xb = nullptr; cudaGetSymbolAddress(&xb, g_Xb);

    const int SMEM_SZ = STAGES * STAGE_BYTES;   // 96 KB
    cudaFuncSetAttribute(gemm_lse_kernel,
                         cudaFuncAttributeMaxDynamicSharedMemorySize, SMEM_SZ);

    // 1. convert W and X to bf16
    cvt_fp32_to_bf16_kernel<<<2048, 256>>>((const float4*)W, (uint4*)wb, (V * H) / 8);
    cvt_fp32_to_bf16_kernel<<<512, 256>>>((const float4*)X, (uint4*)xb, (NTOK * H) / 8);

    // 2. fused GEMM + partial LSE + target-logit capture. x = m_tile (fast) so
    //    CTAs sharing a W slab run concurrently and X stays L2-resident.
    gemm_lse_kernel<<<dim3(M_TILES, V_TILES), THREADS, SMEM_SZ>>>(
        (const __nv_bfloat16*)xb, (const __nv_bfloat16*)wb, bias, target);

    // 3. merge partials (one warp per token), then deterministic mean
    lse_merge_kernel<<<NTOK / 8, 256>>>(target);
    finalize_kernel<<<1, 1024>>>(target, out);
}

// round 13
// speedup vs baseline: 1.1322x; 1.0017x over previous
#include <cuda_runtime.h>
#include <cuda_bf16.h>
#include <cstdint>

// ============================ problem constants =============================
static constexpr int V = 32000;
static constexpr int H = 4096;
static constexpr int NTOK = 4096;
static constexpr int IGNORE_INDEX = -100;

static constexpr int BM = 128;
static constexpr int BN = 128;
static constexpr int BK = 64;            // 64 bf16 = 128B rows (SW128 swizzle)
static constexpr int STAGES = 3;
static constexpr int CHUNKS = H / BK;    // 64
static constexpr int M_TILES = NTOK / BM;  // 32
static constexpr int V_TILES = V / BN;     // 250
static constexpr int THREADS = 256;        // 8 warps: 4 (m) x 2 (n)
static constexpr int A_STAGE_BYTES = BM * BK * 2;   // 16384
static constexpr int B_STAGE_BYTES = BN * BK * 2;   // 16384
static constexpr int STAGE_BYTES = A_STAGE_BYTES + B_STAGE_BYTES;  // 32768

// ============================ device scratch ================================
__device__ __align__(1024) __nv_bfloat16 g_Wb[(size_t)V * H];     // 262 MB
__device__ __align__(1024) __nv_bfloat16 g_Xb[(size_t)NTOK * H];  // 33 MB
// Transposed partials: [tok][v_tile] so lse_merge lanes read consecutive floats
__device__ float g_part_m[(size_t)NTOK * V_TILES];
__device__ float g_part_s[(size_t)NTOK * V_TILES];
__device__ float g_tgt_logit[NTOK];
__device__ float g_nll[NTOK];
__device__ unsigned int g_ticket;   // zero-initialized; last block resets it

// ============================ helpers =======================================
__device__ __forceinline__ uint32_t smem_u32(const void* p) {
    uint32_t a;
    asm("{ .reg .u64 t; cvta.to.shared.u64 t, %1; cvt.u32.u64 %0, t; }" : "=r"(a) : "l"(p));
    return a;
}
// Swizzle<3,4,3> for 128B rows: bits[6:4] ^= bits[9:7]
__device__ __forceinline__ uint32_t swz(uint32_t off) { return off ^ ((off >> 3) & 0x70); }

#define CP_ASYNC_16(dst, src) \
    asm volatile("cp.async.cg.shared.global [%0], [%1], 16;" :: "r"(dst), "l"(src) : "memory")
#define CP_COMMIT() asm volatile("cp.async.commit_group;" ::: "memory")
#define CP_WAIT(n)  asm volatile("cp.async.wait_group %0;" :: "n"(n) : "memory")

#define LDSM_X4(r0, r1, r2, r3, addr) \
    asm volatile("ldmatrix.sync.aligned.m8n8.x4.shared.b16 {%0,%1,%2,%3}, [%4];" \
        : "=r"(r0), "=r"(r1), "=r"(r2), "=r"(r3) : "r"(addr))

#define MMA_16816(c, a, b0, b1) \
    asm volatile("mma.sync.aligned.m16n8k16.row.col.f32.bf16.bf16.f32 " \
        "{%0,%1,%2,%3}, {%4,%5,%6,%7}, {%8,%9}, {%0,%1,%2,%3};" \
        : "+f"((c)[0]), "+f"((c)[1]), "+f"((c)[2]), "+f"((c)[3]) \
        : "r"((a)[0]), "r"((a)[1]), "r"((a)[2]), "r"((a)[3]), "r"(b0), "r"(b1))

// ldmatrix.x4 lane address: 4 8x8 tiles covering (row0..row0+15) x (k16 chunk kk)
__device__ __forceinline__ uint32_t ldsm_addr(uint32_t base, int row0, int lane, int kk) {
    int u = lane >> 3, v = lane & 7;
    int row = row0 + (u & 1) * 8 + v;
    int kb = kk * 32 + (u >> 1) * 16;
    return base + swz((uint32_t)(row * 128 + kb));
}

// ============================ kernels =======================================

// fp32 -> bf16 conversion for BOTH W and X in one launch (grid-stride over
// the concatenated range; W occupies [0, nW8), X occupies [nW8, nW8+nX8)).
__global__ void cvt_both_kernel(const float4* __restrict__ srcW, uint4* __restrict__ dstW, int nW8,
                                const float4* __restrict__ srcX, uint4* __restrict__ dstX, int nX8) {
    int i = blockIdx.x * blockDim.x + threadIdx.x;
    int stride = gridDim.x * blockDim.x;
    int total = nW8 + nX8;
    for (; i < total; i += stride) {
        const float4* src = (i < nW8) ? srcW + 2 * (size_t)i : srcX + 2 * (size_t)(i - nW8);
        uint4* dst = (i < nW8) ? dstW + i : dstX + (i - nW8);
        float4 a = src[0];
        float4 b = src[1];
        __nv_bfloat162 p0 = __floats2bfloat162_rn(a.x, a.y);
        __nv_bfloat162 p1 = __floats2bfloat162_rn(a.z, a.w);
        __nv_bfloat162 p2 = __floats2bfloat162_rn(b.x, b.y);
        __nv_bfloat162 p3 = __floats2bfloat162_rn(b.z, b.w);
        uint4 u;
        u.x = *reinterpret_cast<unsigned int*>(&p0);
        u.y = *reinterpret_cast<unsigned int*>(&p1);
        u.z = *reinterpret_cast<unsigned int*>(&p2);
        u.w = *reinterpret_cast<unsigned int*>(&p3);
        *dst = u;
    }
}

// Fused GEMM + per-tile online softmax partials + in-tile target-logit capture.
// Byte-identical mainloop to the champion kernel.
__global__ void __launch_bounds__(THREADS, 2)
gemm_lse_kernel(const __nv_bfloat16* __restrict__ gX,
                const __nv_bfloat16* __restrict__ gW,
                const float* __restrict__ bias,
                const int* __restrict__ target) {
    extern __shared__ __align__(128) char smem[];
    __shared__ float2 s_red[2][BM];

    const int tid = threadIdx.x;
    const int wid = tid >> 5, lane = tid & 31;
    const int wm = wid & 3, wn = wid >> 2;         // warp tile: rows wm*32, cols wn*64
    const int g = lane >> 2, tg = lane & 3;
    const int m_tile = blockIdx.x, v_tile = blockIdx.y;
    const int m0 = m_tile * BM, v0 = v_tile * BN;
    const uint32_t sbase = smem_u32(smem);

    float acc[2][8][4];
#pragma unroll
    for (int i = 0; i < 2; i++)
#pragma unroll
        for (int j = 0; j < 8; j++)
#pragma unroll
            for (int q = 0; q < 4; q++) acc[i][j][q] = 0.f;

    // ---- precomputed cp.async addressing (per thread, 2 running gmem ptrs)
    const int ld_row = tid >> 3, ld_kc = tid & 7;  // 32 rows per 'it' step
    const __nv_bfloat16* srcA = gX + (size_t)(m0 + ld_row) * H + ld_kc * 8;
    const __nv_bfloat16* srcW = gW + (size_t)(v0 + ld_row) * H + ld_kc * 8;
    const uint32_t dsw = swz((uint32_t)(ld_row * 128 + ld_kc * 16));  // +it*4096 swizzle-safe

    // prologue: stages 0 and 1
#pragma unroll
    for (int s = 0; s < STAGES - 1; s++) {
        uint32_t dA = sbase + s * STAGE_BYTES + dsw;
#pragma unroll
        for (int it = 0; it < 4; it++)
            CP_ASYNC_16(dA + it * 4096, srcA + it * 32 * H);
#pragma unroll
        for (int it = 0; it < 4; it++)
            CP_ASYNC_16(dA + A_STAGE_BYTES + it * 4096, srcW + it * 32 * H);
        CP_COMMIT();
        srcA += BK; srcW += BK;
    }

    int s_cur = 0, s_ld = STAGES - 1;
    for (int c = 0; c < CHUNKS; c++) {
        CP_WAIT(STAGES - 2);
        __syncthreads();

        int cn = c + STAGES - 1;
        const bool doload = cn < CHUNKS;
        const uint32_t sA = sbase + s_cur * STAGE_BYTES;
        const uint32_t sB = sA + A_STAGE_BYTES;
        const uint32_t dL = sbase + s_ld * STAGE_BYTES + dsw;

#pragma unroll
        for (int kk = 0; kk < 4; kk++) {
            uint32_t Af[2][4];
#pragma unroll
            for (int i = 0; i < 2; i++)
                LDSM_X4(Af[i][0], Af[i][1], Af[i][2], Af[i][3],
                        ldsm_addr(sA, wm * 32 + i * 16, lane, kk));
            uint32_t Bf[4][4];
#pragma unroll
            for (int bb = 0; bb < 4; bb++)
                LDSM_X4(Bf[bb][0], Bf[bb][1], Bf[bb][2], Bf[bb][3],
                        ldsm_addr(sB, wn * 64 + bb * 16, lane, kk));

            if (kk == 0 && doload) {       // A-half of next-stage load
#pragma unroll
                for (int it = 0; it < 4; it++)
                    CP_ASYNC_16(dL + it * 4096, srcA + it * 32 * H);
            }
            if (kk == 1 && doload) {       // B-half of next-stage load
#pragma unroll
                for (int it = 0; it < 4; it++)
                    CP_ASYNC_16(dL + A_STAGE_BYTES + it * 4096, srcW + it * 32 * H);
            }

#pragma unroll
            for (int i = 0; i < 2; i++)
#pragma unroll
                for (int j = 0; j < 8; j++)
                    MMA_16816(acc[i][j], Af[i], Bf[j >> 1][j & 1], Bf[j >> 1][(j & 1) + 2]);
        }
        CP_COMMIT();
        srcA += BK; srcW += BK;
        s_cur = (s_cur == STAGES - 1) ? 0 : s_cur + 1;
        s_ld = (s_ld == STAGES - 1) ? 0 : s_ld + 1;
    }

    // ------------------------- epilogue: online softmax --------------------
    const float* bias_v = bias + v0 + wn * 64;
    float b2[8][2];
#pragma unroll
    for (int j = 0; j < 8; j++) {
        b2[j][0] = bias_v[j * 8 + 2 * tg];
        b2[j][1] = bias_v[j * 8 + 2 * tg + 1];
    }

#pragma unroll
    for (int i = 0; i < 2; i++) {
#pragma unroll
        for (int h = 0; h < 2; h++) {
            const int rl = wm * 32 + i * 16 + h * 8 + g;   // local row
            float vals[16];
            float vmax = -1e30f;
#pragma unroll
            for (int j = 0; j < 8; j++)
#pragma unroll
                for (int q = 0; q < 2; q++) {
                    float vv = acc[i][j][h * 2 + q] + b2[j][q];
                    vals[j * 2 + q] = vv;
                    vmax = fmaxf(vmax, vv);
                }
            vmax = fmaxf(vmax, __shfl_xor_sync(0xFFFFFFFFu, vmax, 1));
            vmax = fmaxf(vmax, __shfl_xor_sync(0xFFFFFFFFu, vmax, 2));
            float s = 0.f;
#pragma unroll
            for (int x = 0; x < 16; x++) s += __expf(vals[x] - vmax);
            s += __shfl_xor_sync(0xFFFFFFFFu, s, 1);
            s += __shfl_xor_sync(0xFFFFFFFFu, s, 2);

            // in-tile target-logit capture via direct index arithmetic:
            // col = j*8 + 2*tg + q  ->  owner tg = (tloc>>1)&3, j = tloc>>3, q = tloc&1
            const int t = target[m0 + rl];
            const int tloc = t - v0 - wn * 64;     // col within this warp's 64-col slice
            if (tloc >= 0 && tloc < 64 && ((tloc >> 1) & 3) == tg) {
                const int jj = tloc >> 3, qq = tloc & 1;
                g_tgt_logit[m0 + rl] = vals[jj * 2 + qq];
            }

            if (tg == 0) s_red[wn][rl] = make_float2(vmax, s);
        }
    }
    __syncthreads();
    if (tid < BM) {
        float2 p0 = s_red[0][tid], p1 = s_red[1][tid];
        float m = fmaxf(p0.x, p1.x);
        float s = p0.y * __expf(p0.x - m) + p1.y * __expf(p1.x - m);
        // transposed layout: [tok][v_tile]
        g_part_m[(size_t)(m0 + tid) * V_TILES + v_tile] = m;
        g_part_s[(size_t)(m0 + tid) * V_TILES + v_tile] = s;
    }
}

// one warp per token: merge V_TILES partials -> nll; last block computes mean.
__global__ void lse_merge_kernel(const int* __restrict__ target, float* __restrict__ out) {
    __shared__ bool s_last;
    int tok = blockIdx.x * 8 + (threadIdx.x >> 5);
    int lane = threadIdx.x & 31;
    const float* pm_row = g_part_m + (size_t)tok * V_TILES;
    const float* ps_row = g_part_s + (size_t)tok * V_TILES;
    float m = -1e30f, s = 0.f;
    for (int p = lane; p < V_TILES; p += 32) {
        float pm = pm_row[p];
        float ps = ps_row[p];
        float nm = fmaxf(m, pm);
        s = s * __expf(m - nm) + ps * __expf(pm - nm);
        m = nm;
    }
#pragma unroll
    for (int o = 16; o; o >>= 1) {
        float mo = __shfl_xor_sync(0xFFFFFFFFu, m, o);
        float so = __shfl_xor_sync(0xFFFFFFFFu, s, o);
        float nm = fmaxf(m, mo);
        s = s * __expf(m - nm) + so * __expf(mo - nm);
        m = nm;
    }
    if (lane == 0) {
        float lse = m + __logf(s);
        int t = target[tok];
        g_nll[tok] = (t == IGNORE_INDEX) ? 0.f : (lse - g_tgt_logit[tok]);
    }

    // last-block reduction (deterministic: one block reduces all nll in order)
    __syncthreads();
    if (threadIdx.x == 0) {
        __threadfence();
        unsigned int tkt = atomicAdd(&g_ticket, 1u);
        s_last = (tkt == gridDim.x - 1);
    }
    __syncthreads();
    if (s_last) {
        __threadfence();   // make all blocks' g_nll stores visible
        __shared__ float ssum[256];
        __shared__ int scnt[256];
        int tid = threadIdx.x;
        float acc = 0.f;
        int cnt = 0;
        for (int i = tid; i < NTOK; i += 256) {
            acc += g_nll[i];
            cnt += (target[i] != IGNORE_INDEX);
        }
        ssum[tid] = acc;
        scnt[tid] = cnt;
        __syncthreads();
        for (int o = 128; o; o >>= 1) {
            if (tid < o) { ssum[tid] += ssum[tid + o]; scnt[tid] += scnt[tid + o]; }
            __syncthreads();
        }
        if (tid == 0) {
            out[0] = ssum[0] / (float)scnt[0];
            g_ticket = 0;   // reset for next graph replay
        }
    }
}

// ============================ host launch ===================================
extern "C" void kernel_launch(void* const* d_in, const int* in_sizes, int n_in,
                              void* d_out, int out_size) {
    const float* W = (const float*)d_in[0];
    const float* X = (const float*)d_in[1];
    const int* target = (const int*)d_in[2];     // int32 (jax demotes int64)
    const float* bias = (const float*)d_in[3];
    float* out = (float*)d_out;

    void* wb = nullptr; cudaGetSymbolAddress(&wb, g_Wb);
    void* xb = nullptr; cudaGetSymbolAddress(&xb, g_Xb);

    const int SMEM_SZ = STAGES * STAGE_BYTES;   // 96 KB
    cudaFuncSetAttribute(gemm_lse_kernel,
                         cudaFuncAttributeMaxDynamicSharedMemorySize, SMEM_SZ);

    // 1. convert W and X to bf16 in a single launch
    cvt_both_kernel<<<2048, 256>>>((const float4*)W, (uint4*)wb, (V * H) / 8,
                                   (const float4*)X, (uint4*)xb, (NTOK * H) / 8);

    // 2. fused GEMM + partial LSE + target-logit capture. x = m_tile (fast) so
    //    CTAs sharing a W slab run concurrently and X stays L2-resident.
    gemm_lse_kernel<<<dim3(M_TILES, V_TILES), THREADS, SMEM_SZ>>>(
        (const __nv_bfloat16*)xb, (const __nv_bfloat16*)wb, bias, target);

    // 3. merge partials (one warp per token) + last-block mean
    lse_merge_kernel<<<NTOK / 8, 256>>>(target, out);
}